// round 3
// baseline (speedup 1.0000x reference)
#include <cuda_runtime.h>
#include <cstdint>

// Problem constants (fixed by dataset: IN=(32,3,512,512), OUT=256, scale=0.5)
#define BC      96            // 32*3 planes
#define IN_HW   512
#define OUT_HW  256
#define MAX_T   12            // taps ~10 at scale 0.5; 12 is a safe unroll bound
#define TOH     16            // oh rows per block
#define HALF    260           // padded half-row length for even/odd split (256+4)

// Even/odd split position: smem index for logical column w.
// For a fixed tap, fov[t][ow] has fixed parity across ow -> lanes become
// stride-1 in the split layout -> conflict-free LDS.
__device__ __forceinline__ int pos_of(int w) {
    return (w >> 1) + (w & 1) * HALF;
}

// ---------------------------------------------------------------------------
// Fused bicubic downsample:
//   Phase 1 (H): mid[r][w] = sum_t wh[t][oh0+r] * in[plane][fovh[t][oh0+r]][w]
//                (coalesced float2 global reads, smem writes in split layout)
//   Phase 2 (W): out[plane][oh0+r][ow] = sum_t ww[t][ow] * mid[r][fovw[t][ow]]
//                (conflict-free LDS gathers, coalesced STG)
// Grid = (OUT_HW/TOH, BC), block = 256.
// ---------------------------------------------------------------------------
__global__ __launch_bounds__(256) void resize_fused_kernel(
    const float2* __restrict__ in,    // (BC, IN_HW, IN_HW/2)
    const float*  __restrict__ wh,    // (taps, OUT_HW)  H-axis weights
    const int*    __restrict__ fh,    // (taps, OUT_HW)  H-axis indices
    const float*  __restrict__ ww,    // (taps, OUT_HW)  W-axis weights
    const int*    __restrict__ fw,    // (taps, OUT_HW)  W-axis indices
    float*        __restrict__ out,   // (BC, OUT_HW, OUT_HW)
    int taps)
{
    __shared__ float mid[TOH][2 * HALF];          // split-layout intermediate
    __shared__ float hw_s[MAX_T][TOH];            // per-oh H weights
    __shared__ int   hf_s[MAX_T][TOH];            // per-oh H indices

    const int tid   = threadIdx.x;                // 0..255
    const int oh0   = blockIdx.x * TOH;
    const int plane = blockIdx.y;

    // Cooperative load of the H-axis tables for this oh tile.
    if (tid < taps * TOH) {
        const int t = tid / TOH, r = tid % TOH;
        hw_s[t][r] = wh[t * OUT_HW + oh0 + r];
        hf_s[t][r] = fh[t * OUT_HW + oh0 + r];
    }

    // Per-thread W-axis tables -> registers (position-transformed).
    float wr[MAX_T];
    int   pr[MAX_T];
    #pragma unroll
    for (int t = 0; t < MAX_T; ++t) {
        if (t < taps) {
            wr[t] = ww[t * OUT_HW + tid];
            pr[t] = pos_of(fw[t * OUT_HW + tid]);
        } else { wr[t] = 0.f; pr[t] = 0; }
    }
    __syncthreads();

    // ---------------- Phase 1: H resize (global -> smem) ----------------
    const float2* base = in + (size_t)plane * IN_HW * (IN_HW / 2);
    #pragma unroll 2
    for (int r = 0; r < TOH; ++r) {
        float2 acc = make_float2(0.f, 0.f);
        #pragma unroll
        for (int t = 0; t < MAX_T; ++t) {
            if (t < taps) {
                const float  w = hw_s[t][r];
                const float2 v = base[(size_t)hf_s[t][r] * (IN_HW / 2) + tid];
                acc.x = fmaf(w, v.x, acc.x);
                acc.y = fmaf(w, v.y, acc.y);
            }
        }
        mid[r][tid]        = acc.x;   // even column 2*tid
        mid[r][tid + HALF] = acc.y;   // odd  column 2*tid+1
    }
    __syncthreads();

    // ---------------- Phase 2: W resize (smem -> global) ----------------
    float* obase = out + ((size_t)plane * OUT_HW + oh0) * OUT_HW + tid;
    #pragma unroll 2
    for (int r = 0; r < TOH; ++r) {
        float acc = 0.f;
        #pragma unroll
        for (int t = 0; t < MAX_T; ++t) {
            if (t < taps) acc = fmaf(wr[t], mid[r][pr[t]], acc);
        }
        obase[(size_t)r * OUT_HW] = acc;
    }
}

// ---------------------------------------------------------------------------
// Inputs (metadata order):
//   d_in[0] = in_tensor (f32, 96*512*512)
//   d_in[1] = w2  (f32, taps*256)   d_in[2] = fov2 (i32, taps*256)   -- H axis
//   d_in[3] = w3  (f32, taps*256)   d_in[4] = fov3 (i32, taps*256)   -- W axis
// ---------------------------------------------------------------------------
extern "C" void kernel_launch(void* const* d_in, const int* in_sizes, int n_in,
                              void* d_out, int out_size)
{
    const float* in   = (const float*)d_in[0];
    const float* w2   = (const float*)d_in[1];
    const int*   fov2 = (const int*)  d_in[2];
    const float* w3   = (const float*)d_in[3];
    const int*   fov3 = (const int*)  d_in[4];
    float* out = (float*)d_out;

    const int taps = in_sizes[1] / OUT_HW;

    dim3 grid(OUT_HW / TOH, BC);                  // (16, 96) = 1536 blocks
    resize_fused_kernel<<<grid, 256>>>((const float2*)in, w2, fov2, w3, fov3,
                                       out, taps);
}

// round 4
// speedup vs baseline: 1.9477x; 1.9477x over previous
#include <cuda_runtime.h>
#include <cstdint>

// Problem constants (dataset-fixed: IN=(32,3,512,512), OUT=256, scale=0.5)
#define BC      96
#define IN_HW   512
#define OUT_HW  256
#define TOH     16            // oh rows per block
#define MAX_T   12
#define HALFP   264           // split-layout offset for odd columns (256+8)
#define MIDW    520           // mid row length: 256 even + pad + 256 odd

__device__ __forceinline__ int pos_of(int w) {
    // even/odd split: for fixed tap, fov_w has stride 2 across ow -> pos has
    // stride 1 -> conflict-free LDS.
    return (w >> 1) + (w & 1) * HALFP;
}

// ---------------------------------------------------------------------------
// Fused bicubic downsample, one block = one plane x 16 oh x full W.
// Phase 1 (H): register sliding window over input rows, each input element
//              loaded from global exactly once per block.
// Phase 2 (W): conflict-free smem gathers, coalesced stores.
// ---------------------------------------------------------------------------
template<int TAPS>
__global__ __launch_bounds__(256) void resize_fused(
    const float2* __restrict__ in,    // (BC, IN_HW, IN_HW/2)
    const float*  __restrict__ wh, const int* __restrict__ fh,   // H tables
    const float*  __restrict__ ww, const int* __restrict__ fw,   // W tables
    float*        __restrict__ out)   // (BC, OUT_HW, OUT_HW)
{
    __shared__ float mid[TOH][MIDW];
    __shared__ float hw_s[TAPS][TOH];
    __shared__ int   hf_s[TAPS][TOH];

    const int tid   = threadIdx.x;            // 0..255, owns cols (2t, 2t+1)
    const int oh0   = blockIdx.x * TOH;
    const int plane = blockIdx.y;

    if (tid < TAPS * TOH) {
        const int t = tid / TOH, r = tid % TOH;
        hw_s[t][r] = wh[t * OUT_HW + oh0 + r];
        hf_s[t][r] = fh[t * OUT_HW + oh0 + r];
    }
    __syncthreads();

    // Fast path iff the tile's fov is the unfolded pattern base + 2r + t.
    bool ok = true;
    if (tid < TAPS * TOH) {
        const int t = tid / TOH, r = tid % TOH;
        ok = (hf_s[t][r] == hf_s[0][0] + 2 * r + t);
    }
    const int fast = __syncthreads_and(ok);

    const float2* base = in + (size_t)plane * IN_HW * (IN_HW / 2);

    if (fast) {
        // -------- Phase 1 fast: register sliding window --------
        float2 v[TAPS];
        const int b0 = hf_s[0][0];
        #pragma unroll
        for (int t = 0; t < TAPS; ++t)
            v[t] = base[(b0 + t) * (IN_HW / 2) + tid];

        #pragma unroll
        for (int r = 0; r < TOH; ++r) {
            float2 n0, n1;
            if (r < TOH - 1) {                 // prefetch next 2 rows
                const int nb = b0 + 2 * r + TAPS;
                n0 = base[(size_t)nb       * (IN_HW / 2) + tid];
                n1 = base[(size_t)(nb + 1) * (IN_HW / 2) + tid];
            }
            float2 acc = make_float2(0.f, 0.f);
            #pragma unroll
            for (int t = 0; t < TAPS; ++t) {
                const float w = hw_s[t][r];
                acc.x = fmaf(w, v[t].x, acc.x);
                acc.y = fmaf(w, v[t].y, acc.y);
            }
            mid[r][tid]         = acc.x;       // even col 2*tid
            mid[r][tid + HALFP] = acc.y;       // odd  col 2*tid+1
            #pragma unroll
            for (int t = 0; t < TAPS - 2; ++t) v[t] = v[t + 2];
            if (r < TOH - 1) { v[TAPS - 2] = n0; v[TAPS - 1] = n1; }
        }
    } else {
        // -------- Phase 1 generic (edge tiles with mirror folds) --------
        #pragma unroll 2
        for (int r = 0; r < TOH; ++r) {
            float2 acc = make_float2(0.f, 0.f);
            #pragma unroll
            for (int t = 0; t < TAPS; ++t) {
                const float  w = hw_s[t][r];
                const float2 x = base[(size_t)hf_s[t][r] * (IN_HW / 2) + tid];
                acc.x = fmaf(w, x.x, acc.x);
                acc.y = fmaf(w, x.y, acc.y);
            }
            mid[r][tid]         = acc.x;
            mid[r][tid + HALFP] = acc.y;
        }
    }

    // Phase-2 per-thread tables (loaded here so live ranges don't overlap
    // with the sliding window; latency hidden behind the barrier).
    float wr[TAPS];
    int   pr[TAPS];
    #pragma unroll
    for (int t = 0; t < TAPS; ++t) {
        wr[t] = ww[t * OUT_HW + tid];
        pr[t] = pos_of(fw[t * OUT_HW + tid]);
    }
    __syncthreads();

    // -------- Phase 2: W resize from smem, conflict-free --------
    float* ob = out + ((size_t)plane * OUT_HW + oh0) * OUT_HW + tid;
    #pragma unroll
    for (int r = 0; r < TOH; ++r) {
        float acc = 0.f;
        #pragma unroll
        for (int t = 0; t < TAPS; ++t)
            acc = fmaf(wr[t], mid[r][pr[t]], acc);
        ob[(size_t)r * OUT_HW] = acc;
    }
}

// Generic-taps fallback (correctness safety net; table path everywhere).
__global__ __launch_bounds__(256) void resize_fused_generic(
    const float2* __restrict__ in,
    const float*  __restrict__ wh, const int* __restrict__ fh,
    const float*  __restrict__ ww, const int* __restrict__ fw,
    float*        __restrict__ out, int taps)
{
    __shared__ float mid[TOH][MIDW];
    __shared__ float hw_s[MAX_T][TOH];
    __shared__ int   hf_s[MAX_T][TOH];

    const int tid   = threadIdx.x;
    const int oh0   = blockIdx.x * TOH;
    const int plane = blockIdx.y;

    if (tid < taps * TOH) {
        const int t = tid / TOH, r = tid % TOH;
        hw_s[t][r] = wh[t * OUT_HW + oh0 + r];
        hf_s[t][r] = fh[t * OUT_HW + oh0 + r];
    }
    float wr[MAX_T];
    int   pr[MAX_T];
    #pragma unroll
    for (int t = 0; t < MAX_T; ++t) {
        if (t < taps) {
            wr[t] = ww[t * OUT_HW + tid];
            pr[t] = pos_of(fw[t * OUT_HW + tid]);
        } else { wr[t] = 0.f; pr[t] = 0; }
    }
    __syncthreads();

    const float2* base = in + (size_t)plane * IN_HW * (IN_HW / 2);
    for (int r = 0; r < TOH; ++r) {
        float2 acc = make_float2(0.f, 0.f);
        #pragma unroll
        for (int t = 0; t < MAX_T; ++t) {
            if (t < taps) {
                const float  w = hw_s[t][r];
                const float2 x = base[(size_t)hf_s[t][r] * (IN_HW / 2) + tid];
                acc.x = fmaf(w, x.x, acc.x);
                acc.y = fmaf(w, x.y, acc.y);
            }
        }
        mid[r][tid]         = acc.x;
        mid[r][tid + HALFP] = acc.y;
    }
    __syncthreads();

    float* ob = out + ((size_t)plane * OUT_HW + oh0) * OUT_HW + tid;
    for (int r = 0; r < TOH; ++r) {
        float acc = 0.f;
        #pragma unroll
        for (int t = 0; t < MAX_T; ++t)
            if (t < taps) acc = fmaf(wr[t], mid[r][pr[t]], acc);
        ob[(size_t)r * OUT_HW] = acc;
    }
}

// ---------------------------------------------------------------------------
// Inputs (metadata order): in_tensor, w2, fov2 (H axis), w3, fov3 (W axis)
// ---------------------------------------------------------------------------
extern "C" void kernel_launch(void* const* d_in, const int* in_sizes, int n_in,
                              void* d_out, int out_size)
{
    const float2* in  = (const float2*)d_in[0];
    const float* w2   = (const float*)d_in[1];
    const int*   fov2 = (const int*)  d_in[2];
    const float* w3   = (const float*)d_in[3];
    const int*   fov3 = (const int*)  d_in[4];
    float* out = (float*)d_out;

    const int taps = in_sizes[1] / OUT_HW;
    dim3 grid(OUT_HW / TOH, BC);                  // (16, 96) = 1536 blocks

    switch (taps) {
    case 6:  resize_fused<6> <<<grid, 256>>>(in, w2, fov2, w3, fov3, out); break;
    case 7:  resize_fused<7> <<<grid, 256>>>(in, w2, fov2, w3, fov3, out); break;
    case 8:  resize_fused<8> <<<grid, 256>>>(in, w2, fov2, w3, fov3, out); break;
    case 9:  resize_fused<9> <<<grid, 256>>>(in, w2, fov2, w3, fov3, out); break;
    case 10: resize_fused<10><<<grid, 256>>>(in, w2, fov2, w3, fov3, out); break;
    case 11: resize_fused<11><<<grid, 256>>>(in, w2, fov2, w3, fov3, out); break;
    case 12: resize_fused<12><<<grid, 256>>>(in, w2, fov2, w3, fov3, out); break;
    default: resize_fused_generic<<<grid, 256>>>(in, w2, fov2, w3, fov3, out, taps); break;
    }
}

// round 5
// speedup vs baseline: 2.1234x; 1.0902x over previous
#include <cuda_runtime.h>
#include <cstdint>

// Problem constants (dataset-fixed: IN=(32,3,512,512), OUT=256, scale=0.5)
#define BC      96
#define IN_HW   512
#define OUT_HW  256
#define TOH     16            // oh rows per block (split into two 8-row halves)
#define RPH     8             // rows per half
#define MAX_T   12
#define HALFP   264           // split-layout offset for odd columns (256+8)
#define MIDW    520           // mid row length: 256 even + pad + 256 odd

__device__ __forceinline__ int pos_of(int w) {
    // even/odd split: for fixed tap, fov_w has stride 2 across ow -> pos has
    // stride 1 -> conflict-free LDS.
    return (w >> 1) + (w & 1) * HALFP;
}

// ---------------------------------------------------------------------------
// Fused bicubic downsample. Block = 512 threads = one plane x 16 oh x full W.
// Two 256-thread halves each run an independent 8-row register sliding window
// (phase 1, H axis), then all threads do conflict-free smem W-gathers (phase 2).
// ---------------------------------------------------------------------------
template<int TAPS>
__global__ __launch_bounds__(512) void resize_fused(
    const float2* __restrict__ in,    // (BC, IN_HW, IN_HW/2)
    const float*  __restrict__ wh, const int* __restrict__ fh,   // H tables
    const float*  __restrict__ ww, const int* __restrict__ fw,   // W tables
    float*        __restrict__ out)   // (BC, OUT_HW, OUT_HW)
{
    __shared__ float mid[TOH][MIDW];
    __shared__ float hw_s[TAPS][TOH];
    __shared__ int   hf_s[TAPS][TOH];

    const int tid   = threadIdx.x;            // 0..511
    const int col   = tid & 255;              // owns cols (2*col, 2*col+1)
    const int half  = tid >> 8;               // 0 or 1
    const int r0    = half * RPH;             // first r this half owns
    const int oh0   = blockIdx.x * TOH;
    const int plane = blockIdx.y;

    if (tid < TAPS * TOH) {
        const int t = tid / TOH, r = tid % TOH;
        hw_s[t][r] = wh[t * OUT_HW + oh0 + r];
        hf_s[t][r] = fh[t * OUT_HW + oh0 + r];
    }
    __syncthreads();

    // Fast path iff the tile's fov is the unfolded pattern base + 2r + t.
    bool ok = true;
    if (tid < TAPS * TOH) {
        const int t = tid / TOH, r = tid % TOH;
        ok = (hf_s[t][r] == hf_s[0][0] + 2 * r + t);
    }
    const int fast = __syncthreads_and(ok);

    const float2* base = in + (size_t)plane * IN_HW * (IN_HW / 2);

    if (fast) {
        // -------- Phase 1 fast: per-half register sliding window --------
        float2 v[TAPS];
        const int b0 = hf_s[0][0] + 2 * r0;    // first input row for this half
        #pragma unroll
        for (int t = 0; t < TAPS; ++t)
            v[t] = base[(size_t)(b0 + t) * (IN_HW / 2) + col];

        #pragma unroll
        for (int j = 0; j < RPH; ++j) {
            float2 n0, n1;
            if (j < RPH - 1) {                 // prefetch next 2 rows
                const int nb = b0 + 2 * j + TAPS;
                n0 = base[(size_t)nb       * (IN_HW / 2) + col];
                n1 = base[(size_t)(nb + 1) * (IN_HW / 2) + col];
            }
            const int r = r0 + j;
            // Split accumulator trees (even/odd taps) to halve the FMA chain.
            float ax0 = 0.f, ax1 = 0.f, ay0 = 0.f, ay1 = 0.f;
            #pragma unroll
            for (int t = 0; t < TAPS; t += 2) {
                const float w0 = hw_s[t][r];
                ax0 = fmaf(w0, v[t].x, ax0);
                ay0 = fmaf(w0, v[t].y, ay0);
                if (t + 1 < TAPS) {
                    const float w1 = hw_s[t + 1][r];
                    ax1 = fmaf(w1, v[t + 1].x, ax1);
                    ay1 = fmaf(w1, v[t + 1].y, ay1);
                }
            }
            mid[r][col]         = ax0 + ax1;   // even col 2*col
            mid[r][col + HALFP] = ay0 + ay1;   // odd  col 2*col+1
            #pragma unroll
            for (int t = 0; t < TAPS - 2; ++t) v[t] = v[t + 2];
            if (j < RPH - 1) { v[TAPS - 2] = n0; v[TAPS - 1] = n1; }
        }
    } else {
        // -------- Phase 1 generic (edge tiles with mirror folds) --------
        #pragma unroll
        for (int j = 0; j < RPH; ++j) {
            const int r = r0 + j;
            float2 acc = make_float2(0.f, 0.f);
            #pragma unroll
            for (int t = 0; t < TAPS; ++t) {
                const float  w = hw_s[t][r];
                const float2 x = base[(size_t)hf_s[t][r] * (IN_HW / 2) + col];
                acc.x = fmaf(w, x.x, acc.x);
                acc.y = fmaf(w, x.y, acc.y);
            }
            mid[r][col]         = acc.x;
            mid[r][col + HALFP] = acc.y;
        }
    }

    // Per-thread W tables (hidden behind the barrier).
    float wr[TAPS];
    int   pr[TAPS];
    #pragma unroll
    for (int t = 0; t < TAPS; ++t) {
        wr[t] = ww[t * OUT_HW + col];
        pr[t] = pos_of(fw[t * OUT_HW + col]);
    }
    __syncthreads();

    // -------- Phase 2: W resize from smem, conflict-free --------
    float* ob = out + ((size_t)plane * OUT_HW + oh0 + r0) * OUT_HW + col;
    #pragma unroll
    for (int j = 0; j < RPH; ++j) {
        const int r = r0 + j;
        float a0 = 0.f, a1 = 0.f;
        #pragma unroll
        for (int t = 0; t < TAPS; t += 2) {
            a0 = fmaf(wr[t], mid[r][pr[t]], a0);
            if (t + 1 < TAPS) a1 = fmaf(wr[t + 1], mid[r][pr[t + 1]], a1);
        }
        ob[(size_t)j * OUT_HW] = a0 + a1;
    }
}

// Generic-taps fallback (table path everywhere, 512 threads, same tiling).
__global__ __launch_bounds__(512) void resize_fused_generic(
    const float2* __restrict__ in,
    const float*  __restrict__ wh, const int* __restrict__ fh,
    const float*  __restrict__ ww, const int* __restrict__ fw,
    float*        __restrict__ out, int taps)
{
    __shared__ float mid[TOH][MIDW];
    __shared__ float hw_s[MAX_T][TOH];
    __shared__ int   hf_s[MAX_T][TOH];

    const int tid   = threadIdx.x;
    const int col   = tid & 255;
    const int half  = tid >> 8;
    const int r0    = half * RPH;
    const int oh0   = blockIdx.x * TOH;
    const int plane = blockIdx.y;

    if (tid < taps * TOH) {
        const int t = tid / TOH, r = tid % TOH;
        hw_s[t][r] = wh[t * OUT_HW + oh0 + r];
        hf_s[t][r] = fh[t * OUT_HW + oh0 + r];
    }
    float wr[MAX_T];
    int   pr[MAX_T];
    #pragma unroll
    for (int t = 0; t < MAX_T; ++t) {
        if (t < taps) {
            wr[t] = ww[t * OUT_HW + col];
            pr[t] = pos_of(fw[t * OUT_HW + col]);
        } else { wr[t] = 0.f; pr[t] = 0; }
    }
    __syncthreads();

    const float2* base = in + (size_t)plane * IN_HW * (IN_HW / 2);
    for (int j = 0; j < RPH; ++j) {
        const int r = r0 + j;
        float2 acc = make_float2(0.f, 0.f);
        #pragma unroll
        for (int t = 0; t < MAX_T; ++t) {
            if (t < taps) {
                const float  w = hw_s[t][r];
                const float2 x = base[(size_t)hf_s[t][r] * (IN_HW / 2) + col];
                acc.x = fmaf(w, x.x, acc.x);
                acc.y = fmaf(w, x.y, acc.y);
            }
        }
        mid[r][col]         = acc.x;
        mid[r][col + HALFP] = acc.y;
    }
    __syncthreads();

    float* ob = out + ((size_t)plane * OUT_HW + oh0 + r0) * OUT_HW + col;
    for (int j = 0; j < RPH; ++j) {
        const int r = r0 + j;
        float acc = 0.f;
        #pragma unroll
        for (int t = 0; t < MAX_T; ++t)
            if (t < taps) acc = fmaf(wr[t], mid[r][pr[t]], acc);
        ob[(size_t)j * OUT_HW] = acc;
    }
}

// ---------------------------------------------------------------------------
// Inputs (metadata order): in_tensor, w2, fov2 (H axis), w3, fov3 (W axis)
// ---------------------------------------------------------------------------
extern "C" void kernel_launch(void* const* d_in, const int* in_sizes, int n_in,
                              void* d_out, int out_size)
{
    const float2* in  = (const float2*)d_in[0];
    const float* w2   = (const float*)d_in[1];
    const int*   fov2 = (const int*)  d_in[2];
    const float* w3   = (const float*)d_in[3];
    const int*   fov3 = (const int*)  d_in[4];
    float* out = (float*)d_out;

    const int taps = in_sizes[1] / OUT_HW;
    dim3 grid(OUT_HW / TOH, BC);                  // (16, 96) = 1536 blocks

    switch (taps) {
    case 6:  resize_fused<6> <<<grid, 512>>>(in, w2, fov2, w3, fov3, out); break;
    case 7:  resize_fused<7> <<<grid, 512>>>(in, w2, fov2, w3, fov3, out); break;
    case 8:  resize_fused<8> <<<grid, 512>>>(in, w2, fov2, w3, fov3, out); break;
    case 9:  resize_fused<9> <<<grid, 512>>>(in, w2, fov2, w3, fov3, out); break;
    case 10: resize_fused<10><<<grid, 512>>>(in, w2, fov2, w3, fov3, out); break;
    case 11: resize_fused<11><<<grid, 512>>>(in, w2, fov2, w3, fov3, out); break;
    case 12: resize_fused<12><<<grid, 512>>>(in, w2, fov2, w3, fov3, out); break;
    default: resize_fused_generic<<<grid, 512>>>(in, w2, fov2, w3, fov3, out, taps); break;
    }
}

// round 6
// speedup vs baseline: 2.2060x; 1.0389x over previous
#include <cuda_runtime.h>
#include <cstdint>

// Problem constants (dataset-fixed: IN=(32,3,512,512), OUT=256, scale=0.5)
#define BC      96
#define IN_HW   512
#define OUT_HW  256
#define TOH     16            // oh rows per block (two 8-row halves)
#define RPH     8             // rows per half (even!)
#define MAX_T   12
#define HALFP   260           // odd-column region offset, in 8-byte units
#define MIDW    520           // mid2 row length in 8-byte units

typedef unsigned long long ull;

__device__ __forceinline__ ull pack2(float x, float y) {
    ull r; asm("mov.b64 %0, {%1, %2};" : "=l"(r) : "f"(x), "f"(y)); return r;
}
__device__ __forceinline__ void unpack2(ull v, float& x, float& y) {
    asm("mov.b64 {%0, %1}, %2;" : "=f"(x), "=f"(y) : "l"(v));
}
__device__ __forceinline__ void ffma2(ull& a, ull w, ull v) {
    asm("fma.rn.f32x2 %0, %1, %2, %0;" : "+l"(a) : "l"(w), "l"(v));
}
__device__ __forceinline__ ull fadd2(ull a, ull b) {
    ull r; asm("add.rn.f32x2 %0, %1, %2;" : "=l"(r) : "l"(a), "l"(b)); return r;
}

// even/odd split position (8-byte units): fixed-tap gathers become stride-1.
__device__ __forceinline__ int pos_of(int w) { return (w >> 1) + (w & 1) * HALFP; }

// ---------------------------------------------------------------------------
// Fused bicubic downsample. Block = 512 threads = one plane x 16 oh x full W.
// Phase 1 (H): per-half circular register window, packed f32x2 FMAs,
//              row-PAIR packed store into smem (mid2[rp][p] = {r_even, r_odd}).
// Phase 2 (W): 8 LDS.64 + 8 FFMA2 per row-pair, conflict-free, coalesced STG.
// ---------------------------------------------------------------------------
template<int TAPS>
__global__ __launch_bounds__(512, 3) void resize_fused(
    const ull*   __restrict__ in,     // (BC, IN_HW, 256) column pairs
    const float* __restrict__ wh, const int* __restrict__ fh,   // H tables
    const float* __restrict__ ww, const int* __restrict__ fw,   // W tables
    float*       __restrict__ out)    // (BC, OUT_HW, OUT_HW)
{
    __shared__ ull mid2[TOH / 2][MIDW];       // packed row pairs, split layout
    __shared__ ull hw2 [TAPS][TOH];           // packed (w,w) H weights
    __shared__ int hf_s[TAPS][TOH];

    const int tid   = threadIdx.x;            // 0..511
    const int col   = tid & 255;              // owns input cols (2c, 2c+1)
    const int r0    = (tid >> 8) * RPH;       // first oh row of this half
    const int oh0   = blockIdx.x * TOH;
    const int plane = blockIdx.y;

    if (tid < TAPS * TOH) {
        const int t = tid / TOH, r = tid % TOH;
        const float w = wh[t * OUT_HW + oh0 + r];
        hw2 [t][r] = pack2(w, w);
        hf_s[t][r] = fh[t * OUT_HW + oh0 + r];
    }
    __syncthreads();

    // Fast path iff this tile's H-fov is the unfolded pattern base + 2r + t.
    bool okp = true;
    if (tid < TAPS * TOH) {
        const int t = tid / TOH, r = tid % TOH;
        okp = (hf_s[t][r] == hf_s[0][0] + 2 * r + t);
    }
    const int fast = __syncthreads_and(okp);

    const ull* base = in + (size_t)plane * IN_HW * 256 + col;

    if (fast) {
        // -------- Phase 1 fast: circular register window, FFMA2 --------
        ull v[TAPS];
        const int b0 = hf_s[0][0] + 2 * r0;
        #pragma unroll
        for (int t = 0; t < TAPS; ++t)
            v[t] = base[(size_t)(b0 + t) * 256];

        ull stash = 0;
        #pragma unroll
        for (int j = 0; j < RPH; ++j) {
            const int r = r0 + j;
            ull a0 = 0, a1 = 0;
            // consume the two oldest slots first, then refill them
            ffma2(a0, hw2[0][r], v[(2 * j)     % TAPS]);
            ffma2(a1, hw2[1][r], v[(2 * j + 1) % TAPS]);
            if (j < RPH - 1) {
                v[(2 * j)     % TAPS] = base[(size_t)(b0 + 2 * j + TAPS)     * 256];
                v[(2 * j + 1) % TAPS] = base[(size_t)(b0 + 2 * j + TAPS + 1) * 256];
            }
            #pragma unroll
            for (int t = 2; t < TAPS; ++t) {
                if (t & 1) ffma2(a1, hw2[t][r], v[(2 * j + t) % TAPS]);
                else       ffma2(a0, hw2[t][r], v[(2 * j + t) % TAPS]);
            }
            const ull acc = fadd2(a0, a1);    // (evenColVal, oddColVal)
            if ((j & 1) == 0) stash = acc;
            else {                            // repack across the row pair
                float ex, ey, ox, oy;
                unpack2(stash, ex, ey);
                unpack2(acc,   ox, oy);
                const int rp = (r0 >> 1) + (j >> 1);
                mid2[rp][col]         = pack2(ex, ox);   // even col region
                mid2[rp][col + HALFP] = pack2(ey, oy);   // odd  col region
            }
        }
    } else {
        // -------- Phase 1 generic (edge tiles with mirror folds) --------
        float sx = 0.f, sy = 0.f;
        #pragma unroll
        for (int j = 0; j < RPH; ++j) {
            const int r = r0 + j;
            float ax = 0.f, ay = 0.f;
            #pragma unroll
            for (int t = 0; t < TAPS; ++t) {
                float w, wdup; unpack2(hw2[t][r], w, wdup);
                float x, y;    unpack2(base[(size_t)hf_s[t][r] * 256], x, y);
                ax = fmaf(w, x, ax);
                ay = fmaf(w, y, ay);
            }
            if ((j & 1) == 0) { sx = ax; sy = ay; }
            else {
                const int rp = (r0 >> 1) + (j >> 1);
                mid2[rp][col]         = pack2(sx, ax);
                mid2[rp][col + HALFP] = pack2(sy, ay);
            }
        }
    }

    // Per-thread W tables (packed weights + split positions).
    ull pw[TAPS];
    int pr[TAPS];
    #pragma unroll
    for (int t = 0; t < TAPS; ++t) {
        const float w = ww[t * OUT_HW + col];
        pw[t] = pack2(w, w);
        pr[t] = pos_of(fw[t * OUT_HW + col]);
    }
    __syncthreads();

    // -------- Phase 2: W resize on packed row pairs --------
    float* ob = out + ((size_t)plane * OUT_HW + oh0 + r0) * OUT_HW + col;
    #pragma unroll
    for (int p = 0; p < RPH / 2; ++p) {
        const int rp = (r0 >> 1) + p;
        ull a0 = 0, a1 = 0;
        #pragma unroll
        for (int t = 0; t < TAPS; ++t) {
            if (t & 1) ffma2(a1, pw[t], mid2[rp][pr[t]]);
            else       ffma2(a0, pw[t], mid2[rp][pr[t]]);
        }
        float x, y; unpack2(fadd2(a0, a1), x, y);
        ob[(size_t)(2 * p)     * OUT_HW] = x;   // row r0+2p
        ob[(size_t)(2 * p + 1) * OUT_HW] = y;   // row r0+2p+1
    }
}

// ---------------------------------------------------------------------------
// Generic-taps fallback (correctness safety net; scalar table path).
// ---------------------------------------------------------------------------
__global__ __launch_bounds__(512) void resize_fused_generic(
    const ull*   __restrict__ in,
    const float* __restrict__ wh, const int* __restrict__ fh,
    const float* __restrict__ ww, const int* __restrict__ fw,
    float*       __restrict__ out, int taps)
{
    __shared__ ull mid2[TOH / 2][MIDW];
    __shared__ float hw_s[MAX_T][TOH];
    __shared__ int   hf_s[MAX_T][TOH];

    const int tid   = threadIdx.x;
    const int col   = tid & 255;
    const int r0    = (tid >> 8) * RPH;
    const int oh0   = blockIdx.x * TOH;
    const int plane = blockIdx.y;

    if (tid < taps * TOH) {
        const int t = tid / TOH, r = tid % TOH;
        hw_s[t][r] = wh[t * OUT_HW + oh0 + r];
        hf_s[t][r] = fh[t * OUT_HW + oh0 + r];
    }
    float wr[MAX_T]; int pr[MAX_T];
    #pragma unroll
    for (int t = 0; t < MAX_T; ++t) {
        if (t < taps) {
            wr[t] = ww[t * OUT_HW + col];
            pr[t] = pos_of(fw[t * OUT_HW + col]);
        } else { wr[t] = 0.f; pr[t] = 0; }
    }
    __syncthreads();

    const ull* base = in + (size_t)plane * IN_HW * 256 + col;
    float sx = 0.f, sy = 0.f;
    for (int j = 0; j < RPH; ++j) {
        const int r = r0 + j;
        float ax = 0.f, ay = 0.f;
        #pragma unroll
        for (int t = 0; t < MAX_T; ++t) {
            if (t < taps) {
                float x, y; unpack2(base[(size_t)hf_s[t][r] * 256], x, y);
                ax = fmaf(hw_s[t][r], x, ax);
                ay = fmaf(hw_s[t][r], y, ay);
            }
        }
        if ((j & 1) == 0) { sx = ax; sy = ay; }
        else {
            const int rp = (r0 >> 1) + (j >> 1);
            mid2[rp][col]         = pack2(sx, ax);
            mid2[rp][col + HALFP] = pack2(sy, ay);
        }
    }
    __syncthreads();

    float* ob = out + ((size_t)plane * OUT_HW + oh0 + r0) * OUT_HW + col;
    for (int p = 0; p < RPH / 2; ++p) {
        const int rp = (r0 >> 1) + p;
        float ax = 0.f, ay = 0.f;
        #pragma unroll
        for (int t = 0; t < MAX_T; ++t) {
            if (t < taps) {
                float x, y; unpack2(mid2[rp][pr[t]], x, y);
                ax = fmaf(wr[t], x, ax);
                ay = fmaf(wr[t], y, ay);
            }
        }
        ob[(size_t)(2 * p)     * OUT_HW] = ax;
        ob[(size_t)(2 * p + 1) * OUT_HW] = ay;
    }
}

// ---------------------------------------------------------------------------
// Inputs (metadata order): in_tensor, w2, fov2 (H axis), w3, fov3 (W axis)
// ---------------------------------------------------------------------------
extern "C" void kernel_launch(void* const* d_in, const int* in_sizes, int n_in,
                              void* d_out, int out_size)
{
    const ull*   in   = (const ull*)  d_in[0];
    const float* w2   = (const float*)d_in[1];
    const int*   fov2 = (const int*)  d_in[2];
    const float* w3   = (const float*)d_in[3];
    const int*   fov3 = (const int*)  d_in[4];
    float* out = (float*)d_out;

    const int taps = in_sizes[1] / OUT_HW;
    dim3 grid(OUT_HW / TOH, BC);                  // (16, 96) = 1536 blocks

    switch (taps) {
    case 6:  resize_fused<6> <<<grid, 512>>>(in, w2, fov2, w3, fov3, out); break;
    case 7:  resize_fused<7> <<<grid, 512>>>(in, w2, fov2, w3, fov3, out); break;
    case 8:  resize_fused<8> <<<grid, 512>>>(in, w2, fov2, w3, fov3, out); break;
    case 9:  resize_fused<9> <<<grid, 512>>>(in, w2, fov2, w3, fov3, out); break;
    case 10: resize_fused<10><<<grid, 512>>>(in, w2, fov2, w3, fov3, out); break;
    case 11: resize_fused<11><<<grid, 512>>>(in, w2, fov2, w3, fov3, out); break;
    case 12: resize_fused<12><<<grid, 512>>>(in, w2, fov2, w3, fov3, out); break;
    default: resize_fused_generic<<<grid, 512>>>(in, w2, fov2, w3, fov3, out, taps); break;
    }
}